// round 17
// baseline (speedup 1.0000x reference)
#include <cuda_runtime.h>
#include <cuda_fp16.h>
#include <math.h>

#define TT   2048
#define HD   1024
#define ID   2816
#define NE   8
#define ISD  1408

// ---- routing scratch ----
__device__ int   g_count[NE];
__device__ int   g_tok[NE][TT];
__device__ int   g_slot[NE][TT];
__device__ float g_p[TT][2];
__device__ float g_dp0[(size_t)TT * 2 * HD];
__device__ float g_dp1[(size_t)TT * 2 * HD];
__device__ float g_shp0[(size_t)TT * HD];
__device__ float g_shp1[(size_t)TT * HD];

// ---- fp16 activations only (weights stay fp32 in place) ----
__device__ __half g_x16[(size_t)TT * HD];
__device__ __half g_act[(size_t)TT * 2 * ID];
__device__ __half g_shact[(size_t)TT * ISD];

// =================== helpers ===================
__device__ __forceinline__ unsigned s2u(const void* p) {
    return (unsigned)__cvta_generic_to_shared(p);
}
__device__ __forceinline__ unsigned swz(unsigned o) { return o ^ ((o >> 3) & 0x70); }

__device__ __forceinline__ unsigned pack2h(float f0, float f1) {
    __half2 h = __floats2half2_rn(f0, f1);
    return *(unsigned*)&h;
}
__device__ __forceinline__ void cpasync16(unsigned s, const void* g) {
    asm volatile("cp.async.cg.shared.global [%0], [%1], 16;" :: "r"(s), "l"(g));
}
#define CP_COMMIT() asm volatile("cp.async.commit_group;" ::: "memory")
#define CP_WAIT1()  asm volatile("cp.async.wait_group 1;"  ::: "memory")
#define CP_WAIT0()  asm volatile("cp.async.wait_group 0;"  ::: "memory")

__device__ __forceinline__ void ldsm4(unsigned a, unsigned* r) {
    asm volatile("ldmatrix.sync.aligned.m8n8.x4.shared.b16 {%0,%1,%2,%3}, [%4];"
                 : "=r"(r[0]), "=r"(r[1]), "=r"(r[2]), "=r"(r[3]) : "r"(a));
}
__device__ __forceinline__ void ldsm4t(unsigned a, unsigned* r) {
    asm volatile("ldmatrix.sync.aligned.m8n8.x4.trans.shared.b16 {%0,%1,%2,%3}, [%4];"
                 : "=r"(r[0]), "=r"(r[1]), "=r"(r[2]), "=r"(r[3]) : "r"(a));
}
__device__ __forceinline__ void mma16816(float* c, const unsigned* a, const unsigned* b) {
    asm volatile("mma.sync.aligned.m16n8k16.row.col.f32.f16.f16.f32 "
                 "{%0,%1,%2,%3}, {%4,%5,%6,%7}, {%8,%9}, {%0,%1,%2,%3};"
                 : "+f"(c[0]), "+f"(c[1]), "+f"(c[2]), "+f"(c[3])
                 : "r"(a[0]), "r"(a[1]), "r"(a[2]), "r"(a[3]), "r"(b[0]), "r"(b[1]));
}
__device__ __forceinline__ float silu_mul(float g, float u) {
    return u * g / (1.f + __expf(-g));
}
// pack 2 float4 (8 fp32) -> STS.128 of 8 fp16
__device__ __forceinline__ void sts_pack8(unsigned a, float4 v0, float4 v1) {
    unsigned r0 = pack2h(v0.x, v0.y), r1 = pack2h(v0.z, v0.w);
    unsigned r2 = pack2h(v1.x, v1.y), r3 = pack2h(v1.z, v1.w);
    asm volatile("st.shared.v4.b32 [%0], {%1,%2,%3,%4};"
                 :: "r"(a), "r"(r0), "r"(r1), "r"(r2), "r"(r3));
}

// =================== conv_x: x fp32 -> fp16 ===================
#define NXC (TT * HD / 8)
__global__ void conv_x(const float4* __restrict__ x) {
    int i = blockIdx.x * blockDim.x + threadIdx.x;
    if (i >= NXC) return;
    float4 a = x[2 * i], b = x[2 * i + 1];
    uint4 o;
    o.x = pack2h(a.x, a.y);
    o.y = pack2h(a.z, a.w);
    o.z = pack2h(b.x, b.y);
    o.w = pack2h(b.z, b.w);
    ((uint4*)g_x16)[i] = o;
}

// =================== router ===================
__global__ void zero_counts_kernel() { if (threadIdx.x < NE) g_count[threadIdx.x] = 0; }

__global__ void router_kernel(const float* __restrict__ x, const float* __restrict__ gw) {
    int t = blockIdx.x * blockDim.x + threadIdx.x;
    if (t >= TT) return;
    float lg[NE];
#pragma unroll
    for (int e = 0; e < NE; e++) lg[e] = 0.f;
    const float* xr = x + (size_t)t * HD;
    for (int h = 0; h < HD; h++) {
        float xv = xr[h];
#pragma unroll
        for (int e = 0; e < NE; e++) lg[e] = fmaf(xv, gw[h * NE + e], lg[e]);
    }
    int i0 = 0; float v0 = lg[0];
#pragma unroll
    for (int e = 1; e < NE; e++) if (lg[e] > v0) { v0 = lg[e]; i0 = e; }
    int i1 = -1; float v1 = -INFINITY;
#pragma unroll
    for (int e = 0; e < NE; e++) if (e != i0 && lg[e] > v1) { v1 = lg[e]; i1 = e; }
    float e1 = expf(v1 - v0);
    float inv = 1.f / (1.f + e1);
    g_p[t][0] = inv;
    g_p[t][1] = e1 * inv;
    int p0 = atomicAdd(&g_count[i0], 1);
    g_tok[i0][p0] = t; g_slot[i0][p0] = 0;
    int p1 = atomicAdd(&g_count[i1], 1);
    g_tok[i1][p1] = t; g_slot[i1][p1] = 1;
}

// =================== gate+up HMMA (fp32 B in-loader conversion) ===================
// BM=128, BN=64, BK=64; A via cp.async (fp16), B via LDG(fp32)->cvt->STS
#define GU_A  0u
#define GU_BG 16384u
#define GU_BU 24576u
#define GU_STG 32768u

template<bool SH>
__global__ void __launch_bounds__(256, 2) gateup_hmma(
        const float* __restrict__ BgW, const float* __restrict__ BuW) {
    constexpr int NK = HD / 64;
    constexpr int N_TOT = SH ? ISD : ID;
    const int tid = threadIdx.x, l = tid & 31, wid = tid >> 5;
    const int m0 = blockIdx.x * 128, n0 = blockIdx.y * 64;
    const int e = SH ? 0 : blockIdx.z;
    int cnt = TT;
    if (!SH) { cnt = g_count[e]; if (m0 >= cnt) return; }

    const float* Bg = BgW + (SH ? 0 : (size_t)e * HD * ID) + n0;
    const float* Bu = BuW + (SH ? 0 : (size_t)e * HD * ID) + n0;

    size_t aoff[4];
#pragma unroll
    for (int p = 0; p < 4; p++) {
        int idx = m0 + p * 32 + (tid >> 3);
        if (!SH) {
            int ci = idx < cnt ? idx : cnt - 1;
            aoff[p] = (size_t)g_tok[e][ci] * HD;
        } else {
            aoff[p] = (size_t)idx * HD;
        }
    }

    extern __shared__ char dyn[];
    unsigned sb = (s2u(dyn) + 127) & ~127u;
    const int kseg = tid & 7;
    // B unit mapping (per i in {0,1}): s = i*256+tid, kk = s>>3, c8 = s&7
    const int kkA = tid >> 3, kkB = (256 + tid) >> 3;
    const int c8A = tid & 7,  c8B = tid & 7;

    float4 rb[8];   // staging: [i*4+0..1]=Bg pair, [i*4+2..3]=Bu pair

    auto LDGB = [&](int kt) {
        int k0 = kt * 64;
        const float4* g0 = (const float4*)(Bg + (size_t)(k0 + kkA) * N_TOT + c8A * 8);
        const float4* u0 = (const float4*)(Bu + (size_t)(k0 + kkA) * N_TOT + c8A * 8);
        const float4* g1 = (const float4*)(Bg + (size_t)(k0 + kkB) * N_TOT + c8B * 8);
        const float4* u1 = (const float4*)(Bu + (size_t)(k0 + kkB) * N_TOT + c8B * 8);
        rb[0] = g0[0]; rb[1] = g0[1];
        rb[2] = u0[0]; rb[3] = u0[1];
        rb[4] = g1[0]; rb[5] = g1[1];
        rb[6] = u1[0]; rb[7] = u1[1];
    };
    auto STSB = [&](int kt) {
        unsigned bb = sb + (unsigned)(kt % 3) * GU_STG;
        unsigned d0 = swz((unsigned)kkA * 128 + c8A * 16);
        unsigned d1 = swz((unsigned)kkB * 128 + c8B * 16);
        sts_pack8(bb + GU_BG + d0, rb[0], rb[1]);
        sts_pack8(bb + GU_BU + d0, rb[2], rb[3]);
        sts_pack8(bb + GU_BG + d1, rb[4], rb[5]);
        sts_pack8(bb + GU_BU + d1, rb[6], rb[7]);
    };
    auto LOADA = [&](int kt) {
        unsigned bb = sb + (unsigned)(kt % 3) * GU_STG;
        int k0 = kt * 64;
#pragma unroll
        for (int i = 0; i < 4; i++) {
            unsigned d = swz((unsigned)(i * 32 + (tid >> 3)) * 128 + kseg * 16);
            cpasync16(bb + GU_A + d, g_x16 + aoff[i] + k0 + kseg * 8);
        }
        CP_COMMIT();
    };

    float cg[2][4][4] = {}, cu[2][4][4] = {};
    const int wm = (wid & 3) * 32, wn = (wid >> 2) * 32;
    const unsigned aRowB = (unsigned)(wm + (l & 15)) * 128;
    const unsigned sx = l & 7;
    const unsigned aCx = (l >> 4) & 1;
    const unsigned bKr = (l & 7) + ((l >> 3) & 1) * 8;
    const unsigned bG2 = (l >> 4) & 1;
    const unsigned nq = (unsigned)wn >> 3;
    const unsigned ck0 = ((nq + 0 + bG2) ^ sx) << 4;
    const unsigned ck1 = ((nq + 2 + bG2) ^ sx) << 4;

    auto COMPUTE = [&](int st) {
        unsigned bb = sb + (unsigned)st * GU_STG;
#pragma unroll
        for (int ks = 0; ks < 4; ks++) {
            unsigned cka = (((unsigned)(ks * 2) + aCx) ^ sx) << 4;
            unsigned ah[2][4];
#pragma unroll
            for (int mf = 0; mf < 2; mf++)
                ldsm4(bb + GU_A + aRowB + mf * 2048 + cka, ah[mf]);
            unsigned brow = (unsigned)(ks * 16 + bKr) * 128;
            unsigned bg[8], bu[8];
            ldsm4t(bb + GU_BG + brow + ck0, bg);
            ldsm4t(bb + GU_BG + brow + ck1, bg + 4);
            ldsm4t(bb + GU_BU + brow + ck0, bu);
            ldsm4t(bb + GU_BU + brow + ck1, bu + 4);
#pragma unroll
            for (int mf = 0; mf < 2; mf++)
#pragma unroll
                for (int nf = 0; nf < 4; nf++) {
                    mma16816(cg[mf][nf], ah[mf], bg + nf * 2);
                    mma16816(cu[mf][nf], ah[mf], bu + nf * 2);
                }
        }
    };

    // prologue
    LDGB(0);
    LOADA(0);
    LOADA(1);
    STSB(0);
    LDGB(1);
#pragma unroll 1
    for (int kt = 0; kt < NK; kt++) {
        if (kt + 1 < NK) CP_WAIT1(); else CP_WAIT0();
        __syncthreads();
        if (kt + 2 < NK) LOADA(kt + 2);
        COMPUTE(kt % 3);
        if (kt + 1 < NK) STSB(kt + 1);
        if (kt + 2 < NK) LDGB(kt + 2);
    }

    const int rr = m0 + wm + (l >> 2);
    const int cc0 = n0 + wn + (l & 3) * 2;
    __half* O = SH ? g_shact : g_act;
#pragma unroll
    for (int mf = 0; mf < 2; mf++) {
#pragma unroll
        for (int h = 0; h < 2; h++) {
            int r = rr + mf * 16 + h * 8;
            size_t obase;
            if (!SH) {
                if (r >= cnt) continue;
                int flat = g_tok[e][r] * 2 + g_slot[e][r];
                obase = (size_t)flat * ID;
            } else {
                obase = (size_t)r * ISD;
            }
#pragma unroll
            for (int nf = 0; nf < 4; nf++) {
                float a0 = silu_mul(cg[mf][nf][h * 2 + 0], cu[mf][nf][h * 2 + 0]);
                float a1 = silu_mul(cg[mf][nf][h * 2 + 1], cu[mf][nf][h * 2 + 1]);
                *(unsigned*)(O + obase + cc0 + nf * 8) = pack2h(a0, a1);
            }
        }
    }
}

// =================== expert down HMMA (split-K x2; fp32 B conversion) ===================
#define DN_A 0u
#define DN_B 16384u
#define DN_STG 32768u

__global__ void __launch_bounds__(256, 2) edown_hmma(const float* __restrict__ Wd) {
    const int tid = threadIdx.x, l = tid & 31, wid = tid >> 5;
    const int m0 = blockIdx.x * 128, n0 = blockIdx.y * 128;
    const int z = blockIdx.z;
    const int e = z >> 1, s = z & 1;
    const int nkt = ID / 128;          // 22
    const int kb  = s * (ID / 2);
    int cnt = g_count[e];
    if (m0 >= cnt) return;

    const float* B = Wd + (size_t)e * ID * HD + (size_t)kb * HD + n0;

    size_t aoff[4];
#pragma unroll
    for (int p = 0; p < 4; p++) {
        int idx = m0 + p * 32 + (tid >> 3);
        int ci = idx < cnt ? idx : cnt - 1;
        aoff[p] = (size_t)(g_tok[e][ci] * 2 + g_slot[e][ci]) * ID + kb;
    }

    extern __shared__ char dyn[];
    unsigned sb = (s2u(dyn) + 127) & ~127u;
    const int kseg = tid & 7;
    float4 rb[8];   // 4 units x 2 float4

    auto LDGB = [&](int kt) {
        int k0 = kt * 64;
#pragma unroll
        for (int i = 0; i < 4; i++) {
            int sidx = i * 256 + tid;
            int kk = sidx >> 4, c16 = sidx & 15;
            const float4* p = (const float4*)(B + (size_t)(k0 + kk) * HD + c16 * 8);
            rb[i * 2 + 0] = p[0];
            rb[i * 2 + 1] = p[1];
        }
    };
    auto STSB = [&](int kt) {
        unsigned bb = sb + (unsigned)(kt % 3) * DN_STG;
#pragma unroll
        for (int i = 0; i < 4; i++) {
            int sidx = i * 256 + tid;
            int kk = sidx >> 4, c16 = sidx & 15;
            unsigned d = (unsigned)(c16 >> 3) * 8192 + swz((unsigned)kk * 128 + (c16 & 7) * 16);
            sts_pack8(bb + DN_B + d, rb[i * 2 + 0], rb[i * 2 + 1]);
        }
    };
    auto LOADA = [&](int kt) {
        unsigned bb = sb + (unsigned)(kt % 3) * DN_STG;
        int k0 = kt * 64;
#pragma unroll
        for (int i = 0; i < 4; i++) {
            unsigned d = swz((unsigned)(i * 32 + (tid >> 3)) * 128 + kseg * 16);
            cpasync16(bb + DN_A + d, g_act + aoff[i] + k0 + kseg * 8);
        }
        CP_COMMIT();
    };

    float cc[2][8][4] = {};
    const int wm = (wid & 3) * 32, wn = (wid >> 2) * 64;
    const unsigned aRowB = (unsigned)(wm + (l & 15)) * 128;
    const unsigned sx = l & 7;
    const unsigned aCx = (l >> 4) & 1;
    const unsigned bKr = (l & 7) + ((l >> 3) & 1) * 8;
    const unsigned bG2 = (l >> 4) & 1;
    const unsigned hoff = (unsigned)(wn >> 6) * 8192;
    unsigned ck[4];
#pragma unroll
    for (int j = 0; j < 4; j++) ck[j] = (((unsigned)(2 * j) + bG2) ^ sx) << 4;

    auto COMPUTE = [&](int st) {
        unsigned bb = sb + (unsigned)st * DN_STG;
#pragma unroll
        for (int ks = 0; ks < 4; ks++) {
            unsigned cka = (((unsigned)(ks * 2) + aCx) ^ sx) << 4;
            unsigned ah[2][4];
#pragma unroll
            for (int mf = 0; mf < 2; mf++)
                ldsm4(bb + DN_A + aRowB + mf * 2048 + cka, ah[mf]);
            unsigned brow = (unsigned)(ks * 16 + bKr) * 128;
            unsigned bh[16];
#pragma unroll
            for (int j = 0; j < 4; j++)
                ldsm4t(bb + DN_B + hoff + brow + ck[j], bh + 4 * j);
#pragma unroll
            for (int mf = 0; mf < 2; mf++)
#pragma unroll
                for (int nf = 0; nf < 8; nf++)
                    mma16816(cc[mf][nf], ah[mf], bh + nf * 2);
        }
    };

    LDGB(0);
    LOADA(0);
    LOADA(1);
    STSB(0);
    LDGB(1);
#pragma unroll 1
    for (int kt = 0; kt < nkt; kt++) {
        if (kt + 1 < nkt) CP_WAIT1(); else CP_WAIT0();
        __syncthreads();
        if (kt + 2 < nkt) LOADA(kt + 2);
        COMPUTE(kt % 3);
        if (kt + 1 < nkt) STSB(kt + 1);
        if (kt + 2 < nkt) LDGB(kt + 2);
    }

    const int rr = m0 + wm + (l >> 2);
    const int cc0 = n0 + wn + (l & 3) * 2;
    float* OutP = s ? g_dp1 : g_dp0;
#pragma unroll
    for (int mf = 0; mf < 2; mf++) {
#pragma unroll
        for (int h = 0; h < 2; h++) {
            int r = rr + mf * 16 + h * 8;
            if (r >= cnt) continue;
            int tok = g_tok[e][r], slot = g_slot[e][r];
            float pw = g_p[tok][slot];
            size_t base = (size_t)(tok * 2 + slot) * HD;
#pragma unroll
            for (int nf = 0; nf < 8; nf++) {
                size_t off = base + cc0 + nf * 8;
                *(float2*)(OutP + off) =
                    make_float2(pw * cc[mf][nf][h * 2 + 0], pw * cc[mf][nf][h * 2 + 1]);
            }
        }
    }
}

// =================== shared down HMMA (split-K x2; fp32 B conversion) ===================
#define SD_A 0u
#define SD_B 8192u
#define SD_STG 24576u

__global__ void __launch_bounds__(256, 2) sdown_hmma(const float* __restrict__ Sd) {
    constexpr int NK = (ISD / 2) / 64;   // 11
    const int tid = threadIdx.x, l = tid & 31, wid = tid >> 5;
    const int m0 = blockIdx.x * 64, n0 = blockIdx.y * 128;
    const int s = blockIdx.z;
    const int kb = s * (ISD / 2);

    const float* B = Sd + (size_t)kb * HD + n0;

    size_t aoff[2];
#pragma unroll
    for (int p = 0; p < 2; p++) {
        int idx = m0 + p * 32 + (tid >> 3);
        aoff[p] = (size_t)idx * ISD + kb;
    }

    extern __shared__ char dyn[];
    unsigned sb = (s2u(dyn) + 127) & ~127u;
    const int kseg = tid & 7;
    float4 rb[8];

    auto LDGB = [&](int kt) {
        int k0 = kt * 64;
#pragma unroll
        for (int i = 0; i < 4; i++) {
            int sidx = i * 256 + tid;
            int kk = sidx >> 4, c16 = sidx & 15;
            const float4* p = (const float4*)(B + (size_t)(k0 + kk) * HD + c16 * 8);
            rb[i * 2 + 0] = p[0];
            rb[i * 2 + 1] = p[1];
        }
    };
    auto STSB = [&](int kt) {
        unsigned bb = sb + (unsigned)(kt % 3) * SD_STG;
#pragma unroll
        for (int i = 0; i < 4; i++) {
            int sidx = i * 256 + tid;
            int kk = sidx >> 4, c16 = sidx & 15;
            unsigned d = (unsigned)(c16 >> 3) * 8192 + swz((unsigned)kk * 128 + (c16 & 7) * 16);
            sts_pack8(bb + SD_B + d, rb[i * 2 + 0], rb[i * 2 + 1]);
        }
    };
    auto LOADA = [&](int kt) {
        unsigned bb = sb + (unsigned)(kt % 3) * SD_STG;
        int k0 = kt * 64;
#pragma unroll
        for (int i = 0; i < 2; i++) {
            unsigned d = swz((unsigned)(i * 32 + (tid >> 3)) * 128 + kseg * 16);
            cpasync16(bb + SD_A + d, g_shact + aoff[i] + k0 + kseg * 8);
        }
        CP_COMMIT();
    };

    float cc[2][4][4] = {};
    const int wm = (wid & 1) * 32, wn = (wid >> 1) * 32;
    const unsigned aRowB = (unsigned)(wm + (l & 15)) * 128;
    const unsigned sx = l & 7;
    const unsigned aCx = (l >> 4) & 1;
    const unsigned bKr = (l & 7) + ((l >> 3) & 1) * 8;
    const unsigned bG2 = (l >> 4) & 1;
    const unsigned hoff = (unsigned)(wn >> 6) * 8192;
    const unsigned nq = ((unsigned)wn & 63) >> 3;
    const unsigned ck0 = ((nq + 0 + bG2) ^ sx) << 4;
    const unsigned ck1 = ((nq + 2 + bG2) ^ sx) << 4;

    auto COMPUTE = [&](int st) {
        unsigned bb = sb + (unsigned)st * SD_STG;
#pragma unroll
        for (int ks = 0; ks < 4; ks++) {
            unsigned cka = (((unsigned)(ks * 2) + aCx) ^ sx) << 4;
            unsigned ah[2][4];
#pragma unroll
            for (int mf = 0; mf < 2; mf++)
                ldsm4(bb + SD_A + aRowB + mf * 2048 + cka, ah[mf]);
            unsigned brow = (unsigned)(ks * 16 + bKr) * 128;
            unsigned bh[8];
            ldsm4t(bb + SD_B + hoff + brow + ck0, bh);
            ldsm4t(bb + SD_B + hoff + brow + ck1, bh + 4);
#pragma unroll
            for (int mf = 0; mf < 2; mf++)
#pragma unroll
                for (int nf = 0; nf < 4; nf++)
                    mma16816(cc[mf][nf], ah[mf], bh + nf * 2);
        }
    };

    LDGB(0);
    LOADA(0);
    LOADA(1);
    STSB(0);
    LDGB(1);
#pragma unroll 1
    for (int kt = 0; kt < NK; kt++) {
        if (kt + 1 < NK) CP_WAIT1(); else CP_WAIT0();
        __syncthreads();
        if (kt + 2 < NK) LOADA(kt + 2);
        COMPUTE(kt % 3);
        if (kt + 1 < NK) STSB(kt + 1);
        if (kt + 2 < NK) LDGB(kt + 2);
    }

    const int rr = m0 + wm + (l >> 2);
    const int cc0 = n0 + wn + (l & 3) * 2;
    float* OutP = s ? g_shp1 : g_shp0;
#pragma unroll
    for (int mf = 0; mf < 2; mf++) {
#pragma unroll
        for (int h = 0; h < 2; h++) {
            int r = rr + mf * 16 + h * 8;
#pragma unroll
            for (int nf = 0; nf < 4; nf++) {
                int col = cc0 + nf * 8;
                *(float2*)(OutP + (size_t)r * HD + col) =
                    make_float2(cc[mf][nf][h * 2 + 0], cc[mf][nf][h * 2 + 1]);
            }
        }
    }
}

// =================== final combine ===================
__global__ void combine_kernel(float4* __restrict__ out) {
    int i = blockIdx.x * blockDim.x + threadIdx.x;
    if (i >= TT * HD / 4) return;
    int t  = i / (HD / 4);
    int c4 = i & (HD / 4 - 1);
    size_t b0 = (size_t)(2 * t) * (HD / 4) + c4;
    size_t b1 = b0 + (HD / 4);
    float4 s0 = ((const float4*)g_shp0)[i];
    float4 s1 = ((const float4*)g_shp1)[i];
    float4 a0 = ((const float4*)g_dp0)[b0];
    float4 a1 = ((const float4*)g_dp0)[b1];
    float4 a2 = ((const float4*)g_dp1)[b0];
    float4 a3 = ((const float4*)g_dp1)[b1];
    float4 o;
    o.x = s0.x + s1.x + a0.x + a1.x + a2.x + a3.x;
    o.y = s0.y + s1.y + a0.y + a1.y + a2.y + a3.y;
    o.z = s0.z + s1.z + a0.z + a1.z + a2.z + a3.z;
    o.w = s0.w + s1.w + a0.w + a1.w + a2.w + a3.w;
    out[i] = o;
}

// =================== launch ===================
extern "C" void kernel_launch(void* const* d_in, const int* in_sizes, int n_in,
                              void* d_out, int out_size) {
    const float* x      = (const float*)d_in[0];
    const float* gate_w = (const float*)d_in[1];
    const float* Wg     = (const float*)d_in[2];
    const float* Wu     = (const float*)d_in[3];
    const float* Wd     = (const float*)d_in[4];
    const float* Sg     = (const float*)d_in[5];
    const float* Su     = (const float*)d_in[6];
    const float* Sd     = (const float*)d_in[7];
    float* out = (float*)d_out;

    static cudaStream_t s2 = nullptr;
    static cudaEvent_t evF = nullptr, evR = nullptr, evX = nullptr, evS = nullptr;
    if (!s2) {
        cudaStreamCreateWithFlags(&s2, cudaStreamNonBlocking);
        cudaEventCreateWithFlags(&evF, cudaEventDisableTiming);
        cudaEventCreateWithFlags(&evR, cudaEventDisableTiming);
        cudaEventCreateWithFlags(&evX, cudaEventDisableTiming);
        cudaEventCreateWithFlags(&evS, cudaEventDisableTiming);
        cudaFuncSetAttribute(gateup_hmma<false>, cudaFuncAttributeMaxDynamicSharedMemorySize, 3 * 32768 + 128);
        cudaFuncSetAttribute(gateup_hmma<true>,  cudaFuncAttributeMaxDynamicSharedMemorySize, 3 * 32768 + 128);
        cudaFuncSetAttribute(edown_hmma,         cudaFuncAttributeMaxDynamicSharedMemorySize, 3 * 32768 + 128);
        cudaFuncSetAttribute(sdown_hmma,         cudaFuncAttributeMaxDynamicSharedMemorySize, 3 * 24576 + 128);
    }

    // fork side stream
    cudaEventRecord(evF, 0);
    cudaStreamWaitEvent(s2, evF, 0);

    // #1 (main): x conversion only
    conv_x<<<(NXC + 255) / 256, 256>>>((const float4*)x);
    cudaEventRecord(evX, 0);

    // #2, #3 (side): zero -> router
    zero_counts_kernel<<<1, 32, 0, s2>>>();
    router_kernel<<<TT / 256, 256, 0, s2>>>(x, gate_w);
    cudaEventRecord(evR, s2);

    // #4 (main, profiled): expert gate+up (fp32 weights direct)
    cudaStreamWaitEvent(0, evR, 0);
    dim3 gGU(TT / 128, ID / 64, NE);
    gateup_hmma<false><<<gGU, 256, 3 * 32768 + 128>>>(Wg, Wu);

    // #5, #6 (side): shared gateup -> shared down partials
    cudaStreamWaitEvent(s2, evX, 0);
    dim3 gSGU(TT / 128, ISD / 64);
    gateup_hmma<true><<<gSGU, 256, 3 * 32768 + 128, s2>>>(Sg, Su);
    dim3 gSD(TT / 64, HD / 128, 2);
    sdown_hmma<<<gSD, 256, 3 * 24576 + 128, s2>>>(Sd);
    cudaEventRecord(evS, s2);

    // #7 (main): expert down split-K (fp32 Wd direct)
    dim3 gD(TT / 128, HD / 128, 2 * NE);
    edown_hmma<<<gD, 256, 3 * 32768 + 128>>>(Wd);

    // #8 (main): final combine
    cudaStreamWaitEvent(0, evS, 0);
    combine_kernel<<<(TT * HD / 4 + 255) / 256, 256>>>((float4*)out);
}